// round 11
// baseline (speedup 1.0000x reference)
#include <cuda_runtime.h>
#include <math.h>

typedef unsigned long long ull;

// Problem constants (fixed shapes)
#define Bb 32
#define Cc 3
#define Hh 256
#define Ww 832
#define HWsz (Hh*Ww)          // 212992
#define BC (Bb*Cc)            // 96
#define KDET 100
#define QPR (Ww/4)            // 208 float4-quads per row

#define R_TILE 8
#define TROWS (R_TILE + 2)            // 10
#define NTILES (Hh / R_TILE)          // 32 tiles per slice
#define TILE_CAP (R_TILE * Ww)        // 6656 = worst-case survivors per tile
#define NMS_T 512
#define NWARP (NMS_T / 32)            // 16
#define NQ (R_TILE * QPR)             // 1664 quads per tile

#define PI_F 3.14159265358979323846f
#define HALF_PI_F 1.57079632679489661923f

// ---------------- scratch (device globals; no runtime allocation) ----------------
__device__ ull g_cand[(size_t)BC * HWsz];     // [slice][tile][TILE_CAP]
__device__ int g_tilecnt[BC * NTILES];        // per-tile survivor counts (rewritten each run)
__device__ ull g_top1[BC * KDET];             // per-(b,c) top-100 keys

// key layout: [63:32] = float bits of value (value >= 0 so monotonic as uint)
//             [31:0]  = 0xFFFFFFFF - pixel_index  (larger = smaller index)
// descending key order == jax top_k order (desc value, stable lower-index-first)

__device__ __forceinline__ float fmax3(float a, float b, float c) {
    return fmaxf(a, fmaxf(b, c));
}

// ---------------- kernel 1: smem-tiled 3x3 NMS, fully atomic-free ----------------
__global__ void nms_collect(const float* __restrict__ hm) {
    __shared__ float tile[TROWS][Ww];          // 10 x 832 floats = 33280 B
    __shared__ int   wsum[NWARP];
    __shared__ int   wbase[NWARP];

    int slice = blockIdx.x / NTILES;           // bc in [0,96)
    int tidx  = blockIdx.x - slice * NTILES;   // tile in [0,32)
    int y0    = tidx * R_TILE;
    int tid   = threadIdx.x;
    unsigned lane = tid & 31u;
    int wid = tid >> 5;

    const float ninf = __int_as_float(0xff800000);
    const float* base = hm + (size_t)slice * HWsz;

    // stage rows y0-1 .. y0+R_TILE into smem (halo rows beyond image -> -inf)
    for (int i = tid; i < TROWS * QPR; i += NMS_T) {
        int r = i / QPR, q = i - r * QPR;
        int gy = y0 - 1 + r;
        float4 v;
        if ((unsigned)gy < (unsigned)Hh) v = *(const float4*)(base + gy * Ww + q * 4);
        else v = make_float4(ninf, ninf, ninf, ninf);
        *(float4*)&tile[r][q * 4] = v;
    }
    __syncthreads();

    // phase A: 3x3-max predicate per pixel, per-thread survivor bitmask
    unsigned mask = 0;
    int cnt = 0;
    int slot = 0;
    for (int i = tid; i < NQ; i += NMS_T, slot++) {
        int ly = i / QPR, q = i - ly * QPR;
        int x4 = q * 4;
        float cm0 = ninf, cm1 = ninf, cm2 = ninf, cm3 = ninf, cm4 = ninf, cm5 = ninf;
        float v0 = 0.f, v1 = 0.f, v2 = 0.f, v3 = 0.f;
#pragma unroll
        for (int r = 0; r < 3; r++) {
            const float* row = &tile[ly + r][0];
            float4 f = *(const float4*)&row[x4];
            float l  = (x4 > 0)        ? row[x4 - 1] : ninf;
            float rr = (x4 + 4 < Ww)   ? row[x4 + 4] : ninf;
            cm0 = fmaxf(cm0, l);   cm1 = fmaxf(cm1, f.x); cm2 = fmaxf(cm2, f.y);
            cm3 = fmaxf(cm3, f.z); cm4 = fmaxf(cm4, f.w); cm5 = fmaxf(cm5, rr);
            if (r == 1) { v0 = f.x; v1 = f.y; v2 = f.z; v3 = f.w; }
        }
        if (v0 >= fmax3(cm0, cm1, cm2)) { mask |= 1u << (slot * 4 + 0); cnt++; }
        if (v1 >= fmax3(cm1, cm2, cm3)) { mask |= 1u << (slot * 4 + 1); cnt++; }
        if (v2 >= fmax3(cm2, cm3, cm4)) { mask |= 1u << (slot * 4 + 2); cnt++; }
        if (v3 >= fmax3(cm3, cm4, cm5)) { mask |= 1u << (slot * 4 + 3); cnt++; }
    }

    // block-wide exclusive scan of survivor counts (shuffle scan, no atomics)
    int inc = cnt;
#pragma unroll
    for (int d = 1; d < 32; d <<= 1) {
        int o = __shfl_up_sync(0xffffffffu, inc, d);
        if ((int)lane >= d) inc += o;
    }
    if (lane == 31) wsum[wid] = inc;
    __syncthreads();
    if (wid == 0) {
        int s = (lane < NWARP) ? wsum[lane] : 0;
#pragma unroll
        for (int d = 1; d < NWARP; d <<= 1) {
            int o = __shfl_up_sync(0xffffffffu, s, d);
            if ((int)lane >= d) s += o;
        }
        if (lane < NWARP) wbase[lane] = s - wsum[lane];
        if (lane == NWARP - 1) g_tilecnt[slice * NTILES + tidx] = s;  // total
    }
    __syncthreads();

    // phase B: write survivors at deterministic per-tile slots
    int off = wbase[wid] + (inc - cnt);
    ull* dst = g_cand + (size_t)slice * HWsz + (size_t)tidx * TILE_CAP;
    slot = 0;
    for (int i = tid; i < NQ; i += NMS_T, slot++) {
        unsigned mb = (mask >> (slot * 4)) & 0xFu;
        if (!mb) continue;
        int ly = i / QPR, q = i - ly * QPR;
        int x4 = q * 4;
        const float* row = &tile[ly + 1][0];
        while (mb) {
            int j = __ffs(mb) - 1; mb &= mb - 1;
            float v = row[x4 + j];
            unsigned pix = (unsigned)((y0 + ly) * Ww + x4 + j);
            dst[off++] = ((ull)__float_as_uint(v) << 32) |
                         (ull)(0xFFFFFFFFu - pix);
        }
    }
}

// ---------------- bitonic sort (descending) ----------------
template <int M>
__device__ void bitonic_desc(ull* buf, int tid, int nt) {
    for (int k = 2; k <= M; k <<= 1) {
        for (int j = k >> 1; j > 0; j >>= 1) {
            for (int i = tid; i < M; i += nt) {
                int ij = i ^ j;
                if (ij > i) {
                    bool dir = ((i & k) == 0);          // true -> descending segment
                    ull a = buf[i], b = buf[ij];
                    if ((a < b) == dir) { buf[i] = b; buf[ij] = a; }
                }
            }
            __syncthreads();
        }
    }
}

// warp-aggregated histogram add: one atomic per distinct bin per warp
__device__ __forceinline__ void hist_add(int* hist, int bin) {
    unsigned am = __activemask();
    unsigned peers = __match_any_sync(am, bin);
    int leader = __ffs(peers) - 1;
    if ((int)(threadIdx.x & 31u) == leader) atomicAdd(&hist[bin], __popc(peers));
}

// ---------------- kernel 2: per-(b,c) exact top-100 via 2-level radix select ----------------
__global__ void select_topk() {
    __shared__ int hist[4096];
    __shared__ ull buf[2048];
    __shared__ int s_tc[NTILES];
    __shared__ int s_b1, s_pre1, s_thr, s_m;

    int bc  = blockIdx.x;
    int tid = threadIdx.x;
    int nt  = blockDim.x;
    const ull* cand = g_cand + (size_t)bc * HWsz;

    if (tid < NTILES) s_tc[tid] = g_tilecnt[bc * NTILES + tid];
    for (int i = tid; i < 4096; i += nt) hist[i] = 0;
    if (tid == 0) { s_b1 = -1; s_pre1 = 0; s_thr = 0; s_m = 0; }
    __syncthreads();

    // level 1: 12-bit bins of top value bits (key >> 52), warp-aggregated
    for (int t = 0; t < NTILES; t++) {
        int n = s_tc[t];
        const ull* c = cand + (size_t)t * TILE_CAP;
        for (int i = tid; i < n; i += nt) hist_add(hist, (int)(c[i] >> 52));
    }
    __syncthreads();
    if (tid == 0) {
        int cum = 0;
        for (int b = 4095; b >= 0; b--) {
            int c = hist[b];
            if (cum + c >= KDET) { s_b1 = b; s_pre1 = cum; break; }
            cum += c;
        }
        if (s_b1 < 0) { s_b1 = 0; s_pre1 = 0; }   // fewer than K candidates: take all
    }
    __syncthreads();
    int b1 = s_b1;

    // level 2: next 8 bits within bucket b1, warp-aggregated
    for (int i = tid; i < 256; i += nt) hist[i] = 0;
    __syncthreads();
    for (int t = 0; t < NTILES; t++) {
        int n = s_tc[t];
        const ull* c = cand + (size_t)t * TILE_CAP;
        for (int i = tid; i < n; i += nt) {
            ull k = c[i];
            if ((int)(k >> 52) == b1) hist_add(hist, (int)((k >> 44) & 255));
        }
    }
    __syncthreads();
    if (tid == 0) {
        int cum = s_pre1;
        int b2sel = 0;
        for (int b = 255; b >= 0; b--) {
            int c = hist[b];
            if (cum + c >= KDET) { b2sel = b; break; }
            cum += c;
        }
        s_thr = (b1 << 8) | b2sel;
    }
    __syncthreads();

    // collect everything at/above the 20-bit threshold
    ull thr = (ull)s_thr;
    for (int t = 0; t < NTILES; t++) {
        int n = s_tc[t];
        const ull* c = cand + (size_t)t * TILE_CAP;
        for (int i = tid; i < n; i += nt) {
            ull k = c[i];
            if ((k >> 44) >= thr) {
                int p = atomicAdd(&s_m, 1);
                if (p < 2048) buf[p] = k;
            }
        }
    }
    __syncthreads();
    int m = min(s_m, 2048);

    if (m <= 512) {
        for (int i = tid + m; i < 512; i += nt) buf[i] = 0xFFFFFFFFull;
        __syncthreads();
        bitonic_desc<512>(buf, tid, nt);
    } else {
        for (int i = tid + m; i < 2048; i += nt) buf[i] = 0xFFFFFFFFull;
        __syncthreads();
        bitonic_desc<2048>(buf, tid, nt);
    }

    if (tid < KDET) g_top1[bc * KDET + tid] = buf[tid];
}

// ---------------- kernel 3: per-batch 3-way merge-rank + geometry epilogue ----------------
// The three per-class top-100 lists are already sorted descending. Global rank of
// candidate i = own index + (# strictly-greater keys in each other list, via binary
// search). Re-keyed 64-bit keys are pairwise distinct => ranks are a permutation;
// exactly the jax top_k order. No sort needed.
__global__ void finalize(const float* __restrict__ reg,
                         const float* __restrict__ trans,
                         const float* __restrict__ Kmat,
                         const float* __restrict__ size2,
                         const float* __restrict__ hcam,
                         const float* __restrict__ dimsIn,
                         float* __restrict__ out) {
    __shared__ ull s_key[3 * KDET];
    __shared__ unsigned pixs[3 * KDET];

    int b = blockIdx.x, tid = threadIdx.x;

    unsigned pix = 0;
    if (tid < 3 * KDET) {
        ull k1 = g_top1[b * (3 * KDET) + tid];   // tid = c*100 + j
        pix = 0xFFFFFFFFu - (unsigned)(k1 & 0xFFFFFFFFu);
        if (pix >= (unsigned)HWsz) pix = 0;
        pixs[tid] = pix;
        // re-key with flattened C*K position for the second-stage tie-break
        s_key[tid] = (k1 & 0xFFFFFFFF00000000ull) |
                     (ull)(0xFFFFFFFFu - (unsigned)tid);
    }
    __syncthreads();

    if (tid < 3 * KDET) {
        // own regression gathers (registers; high MLP, overlaps ranking)
        const float* rb = reg + (size_t)b * 4 * HWsz;
        float dv_delta = rb[0 * HWsz + pix];
        float off_u    = rb[1 * HWsz + pix];
        float ori0     = rb[2 * HWsz + pix];
        float ori1     = rb[3 * HWsz + pix];

        ull x = s_key[tid];
        int a = tid / KDET;
        int r = tid - a * KDET;                  // own-list index
#pragma unroll
        for (int L = 0; L < 3; L++) {
            if (L == a) continue;
            const ull* Ls = s_key + L * KDET;
            int lo = 0, hi = KDET;
            while (lo < hi) {                    // count of keys > x (descending list)
                int mid = (lo + hi) >> 1;
                if (Ls[mid] > x) lo = mid + 1; else hi = mid;
            }
            r += lo;
        }

        if (r < KDET) {
            float score = __uint_as_float((unsigned)(x >> 32));
            int clsI = a;

            int ysI = pix / Ww;
            int xsI = pix - ysI * Ww;
            float xs = (float)xsI, ys = (float)ysI;

            // 3x3 inverse of trans_mat (first row needed for img_x)
            const float* T = trans + b * 9;
            float a00=T[0],a01=T[1],a02=T[2],a10=T[3],a11=T[4],a12=T[5],a20=T[6],a21=T[7],a22=T[8];
            float det = a00*(a11*a22 - a12*a21) - a01*(a10*a22 - a12*a20) + a02*(a10*a21 - a11*a20);
            float id = 1.0f / det;
            float i00=(a11*a22-a12*a21)*id, i01=(a02*a21-a01*a22)*id, i02=(a01*a12-a02*a11)*id;

            float ptx = xs + off_u, pty = ys;
            float img_x = i00*ptx + i01*pty + i02;

            const float* Km = Kmat + b * 9;
            float fx = Km[0], cxk = Km[2], fy = Km[4];

            float h = hcam[b];
            float d0 = dimsIn[b*3+0], d1 = dimsIn[b*3+1], d2 = dimsIn[b*3+2];
            if (!isfinite(d0)) d0 = 3.88f;
            if (!isfinite(d1)) d1 = 1.63f;
            if (!isfinite(d2)) d2 = 1.53f;

            float h_ref = h - d1 * 0.5f;
            float fyh = fy * fabsf(h_ref);
            float log_dv_ref = logf(fmaxf(fyh, 1e-7f) / 28.01f);
            float log_dv = fminf(fmaxf(log_dv_ref + dv_delta, -4.0f), 8.0f);
            float depth = fminf(fmaxf(fyh * expf(-log_dv), 0.5f), 120.0f);
            float pxl = (img_x - cxk) * depth / fx;

            float ray = atanf(pxl / (depth + 1e-7f));
            float alpha = atanf(ori0 / (ori1 + 1e-7f)) + (ori1 >= 0.0f ? -HALF_PI_F : HALF_PI_F);
            float roty = alpha + ray;
            if (roty >  PI_F) roty -= 2.0f * PI_F;
            if (roty < -PI_F) roty += 2.0f * PI_F;
            float cs = cosf(roty), sn = sinf(roty);

            const float cx8[8] = {-0.5f, 0.5f, 0.5f, 0.5f, 0.5f,-0.5f,-0.5f,-0.5f};
            const float cy8[8] = {-1.0f,-1.0f, 0.0f, 0.0f,-1.0f,-1.0f, 0.0f, 0.0f};
            const float cz8[8] = {-0.5f,-0.5f,-0.5f, 0.5f, 0.5f, 0.5f, 0.5f,-0.5f};

            float umin =  3.4e38f, umax = -3.4e38f, vmin = 3.4e38f, vmax = -3.4e38f;
#pragma unroll
            for (int i = 0; i < 8; i++) {
                float xc = d0 * cx8[i], yc = d1 * cy8[i], zc = d2 * cz8[i];
                float bx =  cs * xc + sn * zc + pxl;
                float by =  yc + h;
                float bz = -sn * xc + cs * zc + depth;
                float up = Km[0]*bx + Km[1]*by + Km[2]*bz;
                float vp = Km[3]*bx + Km[4]*by + Km[5]*bz;
                float wp = Km[6]*bx + Km[7]*by + Km[8]*bz;
                float u = up / wp, v = vp / wp;
                umin = fminf(umin, u); umax = fmaxf(umax, u);
                vmin = fminf(vmin, v); vmax = fmaxf(vmax, v);
            }
            float img_w = size2[0], img_h = size2[1];
            float xmin = fminf(fmaxf(umin, 0.0f), img_w);
            float xmax = fminf(fmaxf(umax, 0.0f), img_w);
            float ymin = fminf(fmaxf(vmin, 0.0f), img_h);
            float ymax = fminf(fmaxf(vmax, 0.0f), img_h);

            float keep = (score > 0.25f) ? 1.0f : 0.0f;

            float o[14];
            o[0]  = (float)clsI;
            o[1]  = alpha;
            o[2]  = xmin; o[3] = ymin; o[4] = xmax; o[5] = ymax;
            o[6]  = d1;   o[7] = d2;   o[8] = d0;          // roll(dims, -1)
            o[9]  = pxl;  o[10] = h;   o[11] = depth;
            o[12] = roty;
            o[13] = score;

            float* dst = out + (size_t)(b * KDET + r) * 14;
#pragma unroll
            for (int c = 0; c < 14; c++) dst[c] = o[c] * keep;
        }
    }
}

// ---------------- launch ----------------
extern "C" void kernel_launch(void* const* d_in, const int* in_sizes, int n_in,
                              void* d_out, int out_size) {
    const float* hm    = (const float*)d_in[0];
    const float* reg   = (const float*)d_in[1];
    const float* trans = (const float*)d_in[2];
    const float* Kmat  = (const float*)d_in[3];
    const float* size2 = (const float*)d_in[4];
    const float* hcam  = (const float*)d_in[5];
    const float* dims  = (const float*)d_in[6];
    float* out = (float*)d_out;

    nms_collect<<<BC * NTILES, NMS_T>>>(hm);
    select_topk<<<BC, 512>>>();
    finalize<<<Bb, 320>>>(reg, trans, Kmat, size2, hcam, dims, out);
}

// round 12
// speedup vs baseline: 2.0890x; 2.0890x over previous
#include <cuda_runtime.h>
#include <math.h>

typedef unsigned long long ull;

// Problem constants (fixed shapes)
#define Bb 32
#define Cc 3
#define Hh 256
#define Ww 832
#define HWsz (Hh*Ww)          // 212992
#define BC (Bb*Cc)            // 96
#define KDET 100
#define QPR (Ww/4)            // 208 float4-quads per row

#define R_TILE 8
#define TROWS (R_TILE + 2)            // 10
#define NTILES (Hh / R_TILE)          // 32 tiles per slice
#define NMS_T 512
#define NWARP (NMS_T / 32)            // 16
#define NQ (R_TILE * QPR)             // 1664 quads per tile

#define HBINS 16384                   // 14-bit histogram (key bits [63:50])

#define PI_F 3.14159265358979323846f
#define HALF_PI_F 1.57079632679489661923f

// ---------------- scratch (device globals; no runtime allocation) ----------------
__device__ ull g_cand[(size_t)BC * HWsz];     // per-slice contiguous survivor list
__device__ int g_cnt[BC];                     // per-slice survivor count (zeroed by select epilogue)
__device__ int g_hist[BC * HBINS];            // per-slice 14-bit value histogram (zeroed by select epilogue)
__device__ ull g_top1[BC * KDET];             // per-(b,c) top-100 keys

// key layout: [63:32] = float bits of value (value >= 0 so monotonic as uint)
//             [31:0]  = 0xFFFFFFFF - pixel_index  (larger = smaller index)
// descending key order == jax top_k order (desc value, stable lower-index-first)

__device__ __forceinline__ float fmax3(float a, float b, float c) {
    return fmaxf(a, fmaxf(b, c));
}

// ---------------- kernel 1: smem-tiled 3x3 NMS + fused slice histogram ----------------
__global__ void nms_collect(const float* __restrict__ hm) {
    __shared__ float tile[TROWS][Ww];          // 10 x 832 floats = 33280 B
    __shared__ int   wsum[NWARP];
    __shared__ int   wbase[NWARP];
    __shared__ int   s_gbase;

    int slice = blockIdx.x / NTILES;           // bc in [0,96)
    int tidx  = blockIdx.x - slice * NTILES;   // tile in [0,32)
    int y0    = tidx * R_TILE;
    int tid   = threadIdx.x;
    unsigned lane = tid & 31u;
    int wid = tid >> 5;

    const float ninf = __int_as_float(0xff800000);
    const float* base = hm + (size_t)slice * HWsz;

    // stage rows y0-1 .. y0+R_TILE into smem (halo rows beyond image -> -inf)
    for (int i = tid; i < TROWS * QPR; i += NMS_T) {
        int r = i / QPR, q = i - r * QPR;
        int gy = y0 - 1 + r;
        float4 v;
        if ((unsigned)gy < (unsigned)Hh) v = *(const float4*)(base + gy * Ww + q * 4);
        else v = make_float4(ninf, ninf, ninf, ninf);
        *(float4*)&tile[r][q * 4] = v;
    }
    __syncthreads();

    // phase A: 3x3-max predicate per pixel, per-thread survivor bitmask
    unsigned mask = 0;
    int cnt = 0;
    int slot = 0;
    for (int i = tid; i < NQ; i += NMS_T, slot++) {
        int ly = i / QPR, q = i - ly * QPR;
        int x4 = q * 4;
        float cm0 = ninf, cm1 = ninf, cm2 = ninf, cm3 = ninf, cm4 = ninf, cm5 = ninf;
        float v0 = 0.f, v1 = 0.f, v2 = 0.f, v3 = 0.f;
#pragma unroll
        for (int r = 0; r < 3; r++) {
            const float* row = &tile[ly + r][0];
            float4 f = *(const float4*)&row[x4];
            float l  = (x4 > 0)        ? row[x4 - 1] : ninf;
            float rr = (x4 + 4 < Ww)   ? row[x4 + 4] : ninf;
            cm0 = fmaxf(cm0, l);   cm1 = fmaxf(cm1, f.x); cm2 = fmaxf(cm2, f.y);
            cm3 = fmaxf(cm3, f.z); cm4 = fmaxf(cm4, f.w); cm5 = fmaxf(cm5, rr);
            if (r == 1) { v0 = f.x; v1 = f.y; v2 = f.z; v3 = f.w; }
        }
        if (v0 >= fmax3(cm0, cm1, cm2)) { mask |= 1u << (slot * 4 + 0); cnt++; }
        if (v1 >= fmax3(cm1, cm2, cm3)) { mask |= 1u << (slot * 4 + 1); cnt++; }
        if (v2 >= fmax3(cm2, cm3, cm4)) { mask |= 1u << (slot * 4 + 2); cnt++; }
        if (v3 >= fmax3(cm3, cm4, cm5)) { mask |= 1u << (slot * 4 + 3); cnt++; }
    }

    // block-wide exclusive scan of survivor counts (shuffle scan)
    int inc = cnt;
#pragma unroll
    for (int d = 1; d < 32; d <<= 1) {
        int o = __shfl_up_sync(0xffffffffu, inc, d);
        if ((int)lane >= d) inc += o;
    }
    if (lane == 31) wsum[wid] = inc;
    __syncthreads();
    if (wid == 0) {
        int s = (lane < NWARP) ? wsum[lane] : 0;
#pragma unroll
        for (int d = 1; d < NWARP; d <<= 1) {
            int o = __shfl_up_sync(0xffffffffu, s, d);
            if ((int)lane >= d) s += o;
        }
        if (lane < NWARP) wbase[lane] = s - wsum[lane];
        if (lane == NWARP - 1) s_gbase = atomicAdd(&g_cnt[slice], s);
    }
    __syncthreads();

    // phase B: write survivors (contiguous per slice) + slice histogram adds
    int off = s_gbase + wbase[wid] + (inc - cnt);
    ull* dst = g_cand + (size_t)slice * HWsz;
    int* hrow = g_hist + slice * HBINS;
    slot = 0;
    for (int i = tid; i < NQ; i += NMS_T, slot++) {
        unsigned mb = (mask >> (slot * 4)) & 0xFu;
        if (!mb) continue;
        int ly = i / QPR, q = i - ly * QPR;
        int x4 = q * 4;
        const float* row = &tile[ly + 1][0];
        while (mb) {
            int j = __ffs(mb) - 1; mb &= mb - 1;
            float v = row[x4 + j];
            unsigned vb = __float_as_uint(v);
            unsigned pix = (unsigned)((y0 + ly) * Ww + x4 + j);
            dst[off++] = ((ull)vb << 32) | (ull)(0xFFFFFFFFu - pix);
            atomicAdd(&hrow[vb >> 18], 1);     // bin = key bits [63:50]
        }
    }
}

// ---------------- bitonic sort (descending) ----------------
template <int M>
__device__ void bitonic_desc(ull* buf, int tid, int nt) {
    for (int k = 2; k <= M; k <<= 1) {
        for (int j = k >> 1; j > 0; j >>= 1) {
            for (int i = tid; i < M; i += nt) {
                int ij = i ^ j;
                if (ij > i) {
                    bool dir = ((i & k) == 0);          // true -> descending segment
                    ull a = buf[i], b = buf[ij];
                    if ((a < b) == dir) { buf[i] = b; buf[ij] = a; }
                }
            }
            __syncthreads();
        }
    }
}

// ---------------- kernel 2: per-slice top-100 via precomputed histogram ----------------
// One contiguous candidate pass. Threshold bin found by parallel suffix-scan of the
// 14-bit histogram built during nms. Rare (>2048 above-threshold) path refines 8 bits.
__global__ void select_topk() {
    __shared__ ull buf[2048];
    __shared__ int wsc[NWARP];
    __shared__ int s_b1, s_mexp, s_pre1, s_m;
    __shared__ int hist2[256];
    __shared__ ull s_thr;

    int bc  = blockIdx.x;
    int tid = threadIdx.x;
    const int nt = 512;
    int n   = g_cnt[bc];
    const ull* cand = g_cand + (size_t)bc * HWsz;
    const int* gh = g_hist + bc * HBINS;
    unsigned lane = tid & 31u;
    int wid = tid >> 5;

    if (tid == 0) { s_b1 = 0; s_mexp = 0; s_pre1 = 0; s_m = 0; s_thr = 0; }
    __syncthreads();

    // --- parallel suffix-scan: thread t owns bins [16352-32t .. 16383-32t] (descending chunks)
    int lo = HBINS - 32 * (tid + 1);           // ascending base of my chunk
    int cs = 0;
    {
        const int4* p = (const int4*)(gh + lo);
#pragma unroll
        for (int j = 0; j < 8; j++) {
            int4 w = p[j];
            cs += w.x + w.y + w.z + w.w;
        }
    }
    // exclusive scan over thread order (t ascending == bins descending)
    int inc = cs;
#pragma unroll
    for (int d = 1; d < 32; d <<= 1) {
        int o = __shfl_up_sync(0xffffffffu, inc, d);
        if ((int)lane >= d) inc += o;
    }
    if (lane == 31) wsc[wid] = inc;
    __syncthreads();
    int wpre = 0;
    {
        int s = (lane < NWARP) ? wsc[lane] : 0;
#pragma unroll
        for (int d = 1; d < NWARP; d <<= 1) {
            int o = __shfl_up_sync(0xffffffffu, s, d);
            if ((int)lane >= d) s += o;
        }
        s = __shfl_sync(0xffffffffu, s, (wid == 0) ? 0 : (wid - 1));
        wpre = (wid == 0) ? 0 : s;             // sum of full warps above me
    }
    int pre = wpre + (inc - cs);               // items in bins strictly above my chunk
    if (pre < KDET && pre + cs >= KDET) {      // exactly one crossing thread (if n >= K)
        int cum = pre;
        for (int j = 31; j >= 0; j--) {        // walk my chunk from its top bin down
            int bin = lo + j;
            int c = gh[bin];
            if (cum + c >= KDET) { s_b1 = bin; s_pre1 = cum; s_mexp = cum + c; break; }
            cum += c;
        }
    }
    __syncthreads();

    int b1 = s_b1;
    ull thr = (ull)b1 << 50;

    // --- rare refine: too many items share the 14-bit bin -> refine next 8 bits
    if (s_mexp > 2048) {
        for (int i = tid; i < 256; i += nt) hist2[i] = 0;
        __syncthreads();
        for (int i = tid; i < n; i += nt) {
            ull k = cand[i];
            if ((int)(k >> 50) == b1) atomicAdd(&hist2[(int)((k >> 42) & 255)], 1);
        }
        __syncthreads();
        if (tid == 0) {
            int cum = s_pre1;
            int bsel = 0;
            for (int b = 255; b >= 0; b--) {
                int c = hist2[b];
                if (cum + c >= KDET) { bsel = b; break; }
                cum += c;
            }
            s_thr = ((ull)(((unsigned)b1 << 8) | (unsigned)bsel)) << 42;
        }
        __syncthreads();
        thr = s_thr;
    }

    // --- single collect pass (contiguous, high MLP)
    for (int i = tid; i < n; i += nt) {
        ull k = cand[i];
        if (k >= thr) {
            int p = atomicAdd(&s_m, 1);
            if (p < 2048) buf[p] = k;
        }
    }
    __syncthreads();
    int m = min(s_m, 2048);

    if (m <= 512) {
        for (int i = tid + m; i < 512; i += nt) buf[i] = 0xFFFFFFFFull;
        __syncthreads();
        bitonic_desc<512>(buf, tid, nt);
    } else {
        for (int i = tid + m; i < 2048; i += nt) buf[i] = 0xFFFFFFFFull;
        __syncthreads();
        bitonic_desc<2048>(buf, tid, nt);
    }

    if (tid < KDET) g_top1[bc * KDET + tid] = buf[tid];

    // --- epilogue: reset this slice's scratch for the next graph replay
    {
        int4 z = make_int4(0, 0, 0, 0);
        int4* hz = (int4*)(g_hist + bc * HBINS);
        for (int i = tid; i < HBINS / 4; i += nt) hz[i] = z;
        if (tid == 0) g_cnt[bc] = 0;
    }
}

// ---------------- kernel 3: per-batch 3-way merge-rank + geometry epilogue ----------------
// The three per-class top-100 lists are sorted descending. Global rank of candidate i =
// own index + (# strictly-greater keys in each other list, via binary search). Re-keyed
// 64-bit keys are pairwise distinct => ranks form a permutation == jax top_k order.
__global__ void finalize(const float* __restrict__ reg,
                         const float* __restrict__ trans,
                         const float* __restrict__ Kmat,
                         const float* __restrict__ size2,
                         const float* __restrict__ hcam,
                         const float* __restrict__ dimsIn,
                         float* __restrict__ out) {
    __shared__ ull s_key[3 * KDET];
    __shared__ unsigned pixs[3 * KDET];

    int b = blockIdx.x, tid = threadIdx.x;

    unsigned pix = 0;
    if (tid < 3 * KDET) {
        ull k1 = g_top1[b * (3 * KDET) + tid];   // tid = c*100 + j
        pix = 0xFFFFFFFFu - (unsigned)(k1 & 0xFFFFFFFFu);
        if (pix >= (unsigned)HWsz) pix = 0;
        pixs[tid] = pix;
        // re-key with flattened C*K position for the second-stage tie-break
        s_key[tid] = (k1 & 0xFFFFFFFF00000000ull) |
                     (ull)(0xFFFFFFFFu - (unsigned)tid);
    }
    __syncthreads();

    if (tid < 3 * KDET) {
        // own regression gathers (registers; high MLP, overlaps ranking)
        const float* rb = reg + (size_t)b * 4 * HWsz;
        float dv_delta = rb[0 * HWsz + pix];
        float off_u    = rb[1 * HWsz + pix];
        float ori0     = rb[2 * HWsz + pix];
        float ori1     = rb[3 * HWsz + pix];

        ull x = s_key[tid];
        int a = tid / KDET;
        int r = tid - a * KDET;                  // own-list index
#pragma unroll
        for (int L = 0; L < 3; L++) {
            if (L == a) continue;
            const ull* Ls = s_key + L * KDET;
            int lo = 0, hi = KDET;
            while (lo < hi) {                    // count of keys > x (descending list)
                int mid = (lo + hi) >> 1;
                if (Ls[mid] > x) lo = mid + 1; else hi = mid;
            }
            r += lo;
        }

        if (r < KDET) {
            float score = __uint_as_float((unsigned)(x >> 32));
            int clsI = a;

            int ysI = pix / Ww;
            int xsI = pix - ysI * Ww;
            float xs = (float)xsI, ys = (float)ysI;

            // 3x3 inverse of trans_mat (first row needed for img_x)
            const float* T = trans + b * 9;
            float a00=T[0],a01=T[1],a02=T[2],a10=T[3],a11=T[4],a12=T[5],a20=T[6],a21=T[7],a22=T[8];
            float det = a00*(a11*a22 - a12*a21) - a01*(a10*a22 - a12*a20) + a02*(a10*a21 - a11*a20);
            float id = 1.0f / det;
            float i00=(a11*a22-a12*a21)*id, i01=(a02*a21-a01*a22)*id, i02=(a01*a12-a02*a11)*id;

            float ptx = xs + off_u, pty = ys;
            float img_x = i00*ptx + i01*pty + i02;

            const float* Km = Kmat + b * 9;
            float fx = Km[0], cxk = Km[2], fy = Km[4];

            float h = hcam[b];
            float d0 = dimsIn[b*3+0], d1 = dimsIn[b*3+1], d2 = dimsIn[b*3+2];
            if (!isfinite(d0)) d0 = 3.88f;
            if (!isfinite(d1)) d1 = 1.63f;
            if (!isfinite(d2)) d2 = 1.53f;

            float h_ref = h - d1 * 0.5f;
            float fyh = fy * fabsf(h_ref);
            float log_dv_ref = logf(fmaxf(fyh, 1e-7f) / 28.01f);
            float log_dv = fminf(fmaxf(log_dv_ref + dv_delta, -4.0f), 8.0f);
            float depth = fminf(fmaxf(fyh * expf(-log_dv), 0.5f), 120.0f);
            float pxl = (img_x - cxk) * depth / fx;

            float ray = atanf(pxl / (depth + 1e-7f));
            float alpha = atanf(ori0 / (ori1 + 1e-7f)) + (ori1 >= 0.0f ? -HALF_PI_F : HALF_PI_F);
            float roty = alpha + ray;
            if (roty >  PI_F) roty -= 2.0f * PI_F;
            if (roty < -PI_F) roty += 2.0f * PI_F;
            float cs = cosf(roty), sn = sinf(roty);

            const float cx8[8] = {-0.5f, 0.5f, 0.5f, 0.5f, 0.5f,-0.5f,-0.5f,-0.5f};
            const float cy8[8] = {-1.0f,-1.0f, 0.0f, 0.0f,-1.0f,-1.0f, 0.0f, 0.0f};
            const float cz8[8] = {-0.5f,-0.5f,-0.5f, 0.5f, 0.5f, 0.5f, 0.5f,-0.5f};

            float umin =  3.4e38f, umax = -3.4e38f, vmin = 3.4e38f, vmax = -3.4e38f;
#pragma unroll
            for (int i = 0; i < 8; i++) {
                float xc = d0 * cx8[i], yc = d1 * cy8[i], zc = d2 * cz8[i];
                float bx =  cs * xc + sn * zc + pxl;
                float by =  yc + h;
                float bz = -sn * xc + cs * zc + depth;
                float up = Km[0]*bx + Km[1]*by + Km[2]*bz;
                float vp = Km[3]*bx + Km[4]*by + Km[5]*bz;
                float wp = Km[6]*bx + Km[7]*by + Km[8]*bz;
                float u = up / wp, v = vp / wp;
                umin = fminf(umin, u); umax = fmaxf(umax, u);
                vmin = fminf(vmin, v); vmax = fmaxf(vmax, v);
            }
            float img_w = size2[0], img_h = size2[1];
            float xmin = fminf(fmaxf(umin, 0.0f), img_w);
            float xmax = fminf(fmaxf(umax, 0.0f), img_w);
            float ymin = fminf(fmaxf(vmin, 0.0f), img_h);
            float ymax = fminf(fmaxf(vmax, 0.0f), img_h);

            float keep = (score > 0.25f) ? 1.0f : 0.0f;

            float o[14];
            o[0]  = (float)clsI;
            o[1]  = alpha;
            o[2]  = xmin; o[3] = ymin; o[4] = xmax; o[5] = ymax;
            o[6]  = d1;   o[7] = d2;   o[8] = d0;          // roll(dims, -1)
            o[9]  = pxl;  o[10] = h;   o[11] = depth;
            o[12] = roty;
            o[13] = score;

            float* dst = out + (size_t)(b * KDET + r) * 14;
#pragma unroll
            for (int c = 0; c < 14; c++) dst[c] = o[c] * keep;
        }
    }
}

// ---------------- launch ----------------
extern "C" void kernel_launch(void* const* d_in, const int* in_sizes, int n_in,
                              void* d_out, int out_size) {
    const float* hm    = (const float*)d_in[0];
    const float* reg   = (const float*)d_in[1];
    const float* trans = (const float*)d_in[2];
    const float* Kmat  = (const float*)d_in[3];
    const float* size2 = (const float*)d_in[4];
    const float* hcam  = (const float*)d_in[5];
    const float* dims  = (const float*)d_in[6];
    float* out = (float*)d_out;

    nms_collect<<<BC * NTILES, NMS_T>>>(hm);
    select_topk<<<BC, 512>>>();
    finalize<<<Bb, 320>>>(reg, trans, Kmat, size2, hcam, dims, out);
}

// round 13
// speedup vs baseline: 3.5000x; 1.6755x over previous
#include <cuda_runtime.h>
#include <math.h>

typedef unsigned long long ull;

// Problem constants (fixed shapes)
#define Bb 32
#define Cc 3
#define Hh 256
#define Ww 832
#define HWsz (Hh*Ww)          // 212992
#define BC (Bb*Cc)            // 96
#define KDET 100
#define QPR (Ww/4)            // 208 float4-quads per row
#define QPS (Hh*QPR)          // 53248 quads per slice (512 | QPS)

#define NMS_T 512
#define NWARP (NMS_T / 32)    // 16

// Fast-path value filter: survivors below T0F cannot be in the per-slice top-100
// WHENEVER the count of survivors >= T0F is itself >= 100 (all kept keys dominate
// all dropped keys). select_topk verifies the count and falls back to an exact
// full rebuild otherwise. For this input: ~3.1K >= T0F per slice vs K=100 (31x).
#define T0F 0.984375f

#define PI_F 3.14159265358979323846f
#define HALF_PI_F 1.57079632679489661923f

// ---------------- scratch (device globals; no runtime allocation) ----------------
__device__ ull g_cand[(size_t)BC * HWsz];     // per-slice contiguous candidate list
__device__ int g_cnt[BC];                     // per-slice count (reset by select epilogue)
__device__ ull g_top1[BC * KDET];             // per-(b,c) top-100 keys

// key layout: [63:32] = float bits of value (value >= 0 so monotonic as uint)
//             [31:0]  = 0xFFFFFFFF - pixel_index  (larger = smaller index)
// descending key order == jax top_k order (desc value, stable lower-index-first)
__device__ __forceinline__ ull make_key(float v, unsigned pix) {
    return ((ull)__float_as_uint(v) << 32) | (ull)(0xFFFFFFFFu - pix);
}

__device__ __forceinline__ float fmax3(float a, float b, float c) {
    return fmaxf(a, fmaxf(b, c));
}

// ---------------- kernel 1: direct-from-global 3x3 NMS with value pre-filter ----------------
__global__ void nms_collect(const float* __restrict__ hm) {
    __shared__ int wsum[NWARP];
    __shared__ int wbase[NWARP];
    __shared__ int s_gbase;

    int tid = threadIdx.x;
    unsigned lane = tid & 31u;
    int wid = tid >> 5;

    int gid   = blockIdx.x * NMS_T + tid;      // global quad id
    int slice = gid / QPS;                     // block never spans slices (512 | QPS)
    int rem   = gid - slice * QPS;
    int y     = rem / QPR;
    int x4    = (rem - y * QPR) * 4;

    const float ninf = __int_as_float(0xff800000);
    const float* base = hm + (size_t)slice * HWsz;
    const float* rowc = base + y * Ww;

    float4 f = *(const float4*)(rowc + x4);
    unsigned mb = 0;

    float qm = fmaxf(fmaxf(f.x, f.y), fmaxf(f.z, f.w));
    if (qm >= T0F) {
        // full 3x3 check for this quad (halo loads hit L1/L2: heatmap fits in L2)
        float lc = (x4 > 0)      ? rowc[x4 - 1] : ninf;
        float rc = (x4 + 4 < Ww) ? rowc[x4 + 4] : ninf;
        float4 fa; float la, ra;
        if (y > 0) {
            const float* rowa = rowc - Ww;
            fa = *(const float4*)(rowa + x4);
            la = (x4 > 0)      ? rowa[x4 - 1] : ninf;
            ra = (x4 + 4 < Ww) ? rowa[x4 + 4] : ninf;
        } else { fa = make_float4(ninf, ninf, ninf, ninf); la = ra = ninf; }
        float4 fb; float lb, rb;
        if (y + 1 < Hh) {
            const float* rowb = rowc + Ww;
            fb = *(const float4*)(rowb + x4);
            lb = (x4 > 0)      ? rowb[x4 - 1] : ninf;
            rb = (x4 + 4 < Ww) ? rowb[x4 + 4] : ninf;
        } else { fb = make_float4(ninf, ninf, ninf, ninf); lb = rb = ninf; }

        float cm0 = fmax3(la, lc, lb);
        float cm1 = fmax3(fa.x, f.x, fb.x);
        float cm2 = fmax3(fa.y, f.y, fb.y);
        float cm3 = fmax3(fa.z, f.z, fb.z);
        float cm4 = fmax3(fa.w, f.w, fb.w);
        float cm5 = fmax3(ra, rc, rb);

        if (f.x >= T0F && f.x >= fmax3(cm0, cm1, cm2)) mb |= 1u;
        if (f.y >= T0F && f.y >= fmax3(cm1, cm2, cm3)) mb |= 2u;
        if (f.z >= T0F && f.z >= fmax3(cm2, cm3, cm4)) mb |= 4u;
        if (f.w >= T0F && f.w >= fmax3(cm3, cm4, cm5)) mb |= 8u;
    }

    int cnt = __popc(mb);

    // block-wide exclusive scan (order canonicalized later by the full sort)
    int inc = cnt;
#pragma unroll
    for (int d = 1; d < 32; d <<= 1) {
        int o = __shfl_up_sync(0xffffffffu, inc, d);
        if ((int)lane >= d) inc += o;
    }
    if (lane == 31) wsum[wid] = inc;
    __syncthreads();
    if (wid == 0) {
        int s = (lane < NWARP) ? wsum[lane] : 0;
#pragma unroll
        for (int d = 1; d < NWARP; d <<= 1) {
            int o = __shfl_up_sync(0xffffffffu, s, d);
            if ((int)lane >= d) s += o;
        }
        if (lane < NWARP) wbase[lane] = s - wsum[lane];
        if (lane == NWARP - 1) s_gbase = s ? atomicAdd(&g_cnt[slice], s) : 0;
    }
    __syncthreads();

    if (mb) {
        int off = s_gbase + wbase[wid] + (inc - cnt);
        ull* dst = g_cand + (size_t)slice * HWsz;
        unsigned pbase = (unsigned)(y * Ww + x4);
        if (mb & 1u) dst[off++] = make_key(f.x, pbase + 0);
        if (mb & 2u) dst[off++] = make_key(f.y, pbase + 1);
        if (mb & 4u) dst[off++] = make_key(f.z, pbase + 2);
        if (mb & 8u) dst[off++] = make_key(f.w, pbase + 3);
    }
}

// ---------------- bitonic sort (descending) ----------------
template <int M>
__device__ void bitonic_desc(ull* buf, int tid, int nt) {
    for (int k = 2; k <= M; k <<= 1) {
        for (int j = k >> 1; j > 0; j >>= 1) {
            for (int i = tid; i < M; i += nt) {
                int ij = i ^ j;
                if (ij > i) {
                    bool dir = ((i & k) == 0);          // true -> descending segment
                    ull a = buf[i], b = buf[ij];
                    if ((a < b) == dir) { buf[i] = b; buf[ij] = a; }
                }
            }
            __syncthreads();
        }
    }
}

// ---------------- kernel 2: per-slice exact top-100, leveled 12-bit radix ----------------
__global__ void select_topk(const float* __restrict__ hm) {
    __shared__ int hist[4096];
    __shared__ ull buf[2048];
    __shared__ int wsc[NWARP];
    __shared__ int s_bin, s_pre, s_mexp, s_m;

    int bc  = blockIdx.x;
    int tid = threadIdx.x;
    const int nt = 512;
    unsigned lane = tid & 31u;
    int wid = tid >> 5;

    int n = g_cnt[bc];
    ull* cand = g_cand + (size_t)bc * HWsz;

    // ---- exact fallback: too few fast candidates -> rebuild ALL survivors inline.
    // (Never executes for this input: fast count ~3.1K >> 100.)
    if (n < KDET) {
        if (tid == 0) s_m = 0;
        __syncthreads();
        const float* base = hm + (size_t)bc * HWsz;
        for (int p = tid; p < HWsz; p += nt) {
            float v = base[p];
            int y = p / Ww, x = p - y * Ww;
            bool sv = true;
#pragma unroll
            for (int dy = -1; dy <= 1; dy++)
#pragma unroll
                for (int dx = -1; dx <= 1; dx++) {
                    if ((dy | dx) == 0) continue;
                    int yy = y + dy, xx = x + dx;
                    if ((unsigned)yy < (unsigned)Hh && (unsigned)xx < (unsigned)Ww)
                        sv = sv && (v >= base[yy * Ww + xx]);
                }
            if (sv) { int o = atomicAdd(&s_m, 1); cand[o] = make_key(v, (unsigned)p); }
        }
        __syncthreads();
        n = s_m;
        __syncthreads();
    }
    if (tid == 0) s_m = 0;

    // ---- leveled 12-bit radix: find pref with |{k >= pref}| in [K, 2048]
    ull pref = 0;
    int prevcum = 0;
    int shift = 52;
#pragma unroll 1
    for (int level = 0; level < 4; level++) {
        for (int i = tid; i < 4096; i += nt) hist[i] = 0;
        if (tid == 0) { s_bin = 0; s_pre = prevcum; s_mexp = prevcum; }
        __syncthreads();

        bool top = (level == 0);
        for (int i = tid; i < n; i += nt) {
            ull k = cand[i];
            if (top || ((k >> (shift + 12)) == (pref >> (shift + 12))))
                atomicAdd(&hist[(int)((k >> shift) & 4095)], 1);
        }
        __syncthreads();

        // parallel suffix scan: thread t owns descending chunk of 8 bins
        int lo = 4096 - 8 * (tid + 1);
        int cs = 0;
#pragma unroll
        for (int j = 0; j < 8; j++) cs += hist[lo + j];
        int inc = cs;
#pragma unroll
        for (int d = 1; d < 32; d <<= 1) {
            int o = __shfl_up_sync(0xffffffffu, inc, d);
            if ((int)lane >= d) inc += o;
        }
        if (lane == 31) wsc[wid] = inc;
        __syncthreads();
        int wpre = 0;
        {
            int s = (lane < NWARP) ? wsc[lane] : 0;
#pragma unroll
            for (int d = 1; d < NWARP; d <<= 1) {
                int o = __shfl_up_sync(0xffffffffu, s, d);
                if ((int)lane >= d) s += o;
            }
            s = __shfl_sync(0xffffffffu, s, (wid == 0) ? 0 : (wid - 1));
            wpre = (wid == 0) ? 0 : s;
        }
        int pre = prevcum + wpre + (inc - cs);
        if (pre < KDET && pre + cs >= KDET) {     // exactly one crossing thread
            int cum = pre;
            for (int j = 7; j >= 0; j--) {
                int bin = lo + j;
                int c = hist[bin];
                if (cum + c >= KDET) { s_bin = bin; s_pre = cum; s_mexp = cum + c; break; }
                cum += c;
            }
        }
        __syncthreads();
        pref |= ((ull)s_bin) << shift;
        prevcum = s_pre;
        int mexp = s_mexp;
        __syncthreads();
        if (mexp <= 2048 || shift == 16) break;
        shift -= 12;
    }

    // ---- single collect pass + sort
    for (int i = tid; i < n; i += nt) {
        ull k = cand[i];
        if (k >= pref) {
            int p = atomicAdd(&s_m, 1);
            if (p < 2048) buf[p] = k;
        }
    }
    __syncthreads();
    int m = min(s_m, 2048);

    if (m <= 512) {
        for (int i = tid + m; i < 512; i += nt) buf[i] = 0xFFFFFFFFull;  // value 0, pix 0
        __syncthreads();
        bitonic_desc<512>(buf, tid, nt);
    } else {
        for (int i = tid + m; i < 2048; i += nt) buf[i] = 0xFFFFFFFFull;
        __syncthreads();
        bitonic_desc<2048>(buf, tid, nt);
    }

    if (tid < KDET) g_top1[bc * KDET + tid] = buf[tid];

    // epilogue: reset counter for the next graph replay
    if (tid == 0) g_cnt[bc] = 0;
}

// ---------------- kernel 3: per-batch 3-way merge-rank + geometry epilogue ----------------
// Three per-class top-100 lists are sorted descending. Global rank of candidate i =
// own index + (# strictly-greater keys in the other lists via binary search). Re-keyed
// 64-bit keys are pairwise distinct => ranks form a permutation == jax top_k order.
__global__ void finalize(const float* __restrict__ reg,
                         const float* __restrict__ trans,
                         const float* __restrict__ Kmat,
                         const float* __restrict__ size2,
                         const float* __restrict__ hcam,
                         const float* __restrict__ dimsIn,
                         float* __restrict__ out) {
    __shared__ ull s_key[3 * KDET];

    int b = blockIdx.x, tid = threadIdx.x;

    unsigned pix = 0;
    if (tid < 3 * KDET) {
        ull k1 = g_top1[b * (3 * KDET) + tid];   // tid = c*100 + j
        pix = 0xFFFFFFFFu - (unsigned)(k1 & 0xFFFFFFFFu);
        if (pix >= (unsigned)HWsz) pix = 0;
        // re-key with flattened C*K position for the second-stage tie-break
        s_key[tid] = (k1 & 0xFFFFFFFF00000000ull) |
                     (ull)(0xFFFFFFFFu - (unsigned)tid);
    }
    __syncthreads();

    if (tid < 3 * KDET) {
        // own regression gathers (issued early; high MLP overlaps the ranking)
        const float* rb = reg + (size_t)b * 4 * HWsz;
        float dv_delta = rb[0 * HWsz + pix];
        float off_u    = rb[1 * HWsz + pix];
        float ori0     = rb[2 * HWsz + pix];
        float ori1     = rb[3 * HWsz + pix];

        ull x = s_key[tid];
        int a = tid / KDET;
        int r = tid - a * KDET;                  // own-list index
#pragma unroll
        for (int L = 0; L < 3; L++) {
            if (L == a) continue;
            const ull* Ls = s_key + L * KDET;
            int lo = 0, hi = KDET;
            while (lo < hi) {                    // count of keys > x (descending list)
                int mid = (lo + hi) >> 1;
                if (Ls[mid] > x) lo = mid + 1; else hi = mid;
            }
            r += lo;
        }

        if (r < KDET) {
            float score = __uint_as_float((unsigned)(x >> 32));
            int clsI = a;

            int ysI = pix / Ww;
            int xsI = pix - ysI * Ww;
            float xs = (float)xsI, ys = (float)ysI;

            // 3x3 inverse of trans_mat (first row needed for img_x)
            const float* T = trans + b * 9;
            float a00=T[0],a01=T[1],a02=T[2],a10=T[3],a11=T[4],a12=T[5],a20=T[6],a21=T[7],a22=T[8];
            float det = a00*(a11*a22 - a12*a21) - a01*(a10*a22 - a12*a20) + a02*(a10*a21 - a11*a20);
            float id = 1.0f / det;
            float i00=(a11*a22-a12*a21)*id, i01=(a02*a21-a01*a22)*id, i02=(a01*a12-a02*a11)*id;

            float ptx = xs + off_u, pty = ys;
            float img_x = i00*ptx + i01*pty + i02;

            const float* Km = Kmat + b * 9;
            float fx = Km[0], cxk = Km[2], fy = Km[4];

            float h = hcam[b];
            float d0 = dimsIn[b*3+0], d1 = dimsIn[b*3+1], d2 = dimsIn[b*3+2];
            if (!isfinite(d0)) d0 = 3.88f;
            if (!isfinite(d1)) d1 = 1.63f;
            if (!isfinite(d2)) d2 = 1.53f;

            float h_ref = h - d1 * 0.5f;
            float fyh = fy * fabsf(h_ref);
            float log_dv_ref = logf(fmaxf(fyh, 1e-7f) / 28.01f);
            float log_dv = fminf(fmaxf(log_dv_ref + dv_delta, -4.0f), 8.0f);
            float depth = fminf(fmaxf(fyh * expf(-log_dv), 0.5f), 120.0f);
            float pxl = (img_x - cxk) * depth / fx;

            float ray = atanf(pxl / (depth + 1e-7f));
            float alpha = atanf(ori0 / (ori1 + 1e-7f)) + (ori1 >= 0.0f ? -HALF_PI_F : HALF_PI_F);
            float roty = alpha + ray;
            if (roty >  PI_F) roty -= 2.0f * PI_F;
            if (roty < -PI_F) roty += 2.0f * PI_F;
            float cs = cosf(roty), sn = sinf(roty);

            const float cx8[8] = {-0.5f, 0.5f, 0.5f, 0.5f, 0.5f,-0.5f,-0.5f,-0.5f};
            const float cy8[8] = {-1.0f,-1.0f, 0.0f, 0.0f,-1.0f,-1.0f, 0.0f, 0.0f};
            const float cz8[8] = {-0.5f,-0.5f,-0.5f, 0.5f, 0.5f, 0.5f, 0.5f,-0.5f};

            float umin =  3.4e38f, umax = -3.4e38f, vmin = 3.4e38f, vmax = -3.4e38f;
#pragma unroll
            for (int i = 0; i < 8; i++) {
                float xc = d0 * cx8[i], yc = d1 * cy8[i], zc = d2 * cz8[i];
                float bx =  cs * xc + sn * zc + pxl;
                float by =  yc + h;
                float bz = -sn * xc + cs * zc + depth;
                float up = Km[0]*bx + Km[1]*by + Km[2]*bz;
                float vp = Km[3]*bx + Km[4]*by + Km[5]*bz;
                float wp = Km[6]*bx + Km[7]*by + Km[8]*bz;
                float u = up / wp, v = vp / wp;
                umin = fminf(umin, u); umax = fmaxf(umax, u);
                vmin = fminf(vmin, v); vmax = fmaxf(vmax, v);
            }
            float img_w = size2[0], img_h = size2[1];
            float xmin = fminf(fmaxf(umin, 0.0f), img_w);
            float xmax = fminf(fmaxf(umax, 0.0f), img_w);
            float ymin = fminf(fmaxf(vmin, 0.0f), img_h);
            float ymax = fminf(fmaxf(vmax, 0.0f), img_h);

            float keep = (score > 0.25f) ? 1.0f : 0.0f;

            float o[14];
            o[0]  = (float)clsI;
            o[1]  = alpha;
            o[2]  = xmin; o[3] = ymin; o[4] = xmax; o[5] = ymax;
            o[6]  = d1;   o[7] = d2;   o[8] = d0;          // roll(dims, -1)
            o[9]  = pxl;  o[10] = h;   o[11] = depth;
            o[12] = roty;
            o[13] = score;

            float* dst = out + (size_t)(b * KDET + r) * 14;
#pragma unroll
            for (int c = 0; c < 14; c++) dst[c] = o[c] * keep;
        }
    }
}

// ---------------- launch ----------------
extern "C" void kernel_launch(void* const* d_in, const int* in_sizes, int n_in,
                              void* d_out, int out_size) {
    const float* hm    = (const float*)d_in[0];
    const float* reg   = (const float*)d_in[1];
    const float* trans = (const float*)d_in[2];
    const float* Kmat  = (const float*)d_in[3];
    const float* size2 = (const float*)d_in[4];
    const float* hcam  = (const float*)d_in[5];
    const float* dims  = (const float*)d_in[6];
    float* out = (float*)d_out;

    nms_collect<<<(BC * QPS) / NMS_T, NMS_T>>>(hm);   // 9984 blocks
    select_topk<<<BC, 512>>>(hm);
    finalize<<<Bb, 320>>>(reg, trans, Kmat, size2, hcam, dims, out);
}

// round 14
// speedup vs baseline: 4.1299x; 1.1800x over previous
#include <cuda_runtime.h>
#include <math.h>

typedef unsigned long long ull;

// Problem constants (fixed shapes)
#define Bb 32
#define Cc 3
#define Hh 256
#define Ww 832
#define HWsz (Hh*Ww)          // 212992
#define BC (Bb*Cc)            // 96
#define KDET 100
#define QPR (Ww/4)            // 208 float4-quads per row
#define QPS (Hh*QPR)          // 53248 quads per slice

#define NMS_T 512
#define NWARP (NMS_T / 32)    // 16
#define QPT 4                 // quads per thread
#define CHUNK (NMS_T * QPT)   // 2048 quads per block
#define BLK_PER_SLICE (QPS / CHUNK)   // 26

// Fast-path value filter: survivors below T0F cannot be in the per-slice top-100
// WHENEVER the count of survivors >= T0F is itself >= 100 (all kept keys dominate
// all dropped keys). select_topk verifies the count and falls back to an exact
// full rebuild otherwise. For this input: ~3.1K >= T0F per slice vs K=100 (31x).
#define T0F 0.984375f

#define PI_F 3.14159265358979323846f
#define HALF_PI_F 1.57079632679489661923f

// ---------------- scratch (device globals; no runtime allocation) ----------------
__device__ ull g_cand[(size_t)BC * HWsz];     // per-slice contiguous candidate list
__device__ int g_cnt[BC];                     // per-slice count (reset by select epilogue)
__device__ ull g_top1[BC * KDET];             // per-(b,c) top-100 keys

// key layout: [63:32] = float bits of value (value >= 0 so monotonic as uint)
//             [31:0]  = 0xFFFFFFFF - pixel_index  (larger = smaller index)
// descending key order == jax top_k order (desc value, stable lower-index-first)
__device__ __forceinline__ ull make_key(float v, unsigned pix) {
    return ((ull)__float_as_uint(v) << 32) | (ull)(0xFFFFFFFFu - pix);
}

__device__ __forceinline__ float fmax3(float a, float b, float c) {
    return fmaxf(a, fmaxf(b, c));
}

// 3x3 NMS check for one quad at (y, x4); returns 4-bit survivor mask.
__device__ __forceinline__ unsigned nms_quad(const float* __restrict__ rowc,
                                             float4 f, int y, int x4) {
    const float ninf = __int_as_float(0xff800000);
    unsigned mb = 0;
    float lc = (x4 > 0)      ? rowc[x4 - 1] : ninf;
    float rc = (x4 + 4 < Ww) ? rowc[x4 + 4] : ninf;
    float4 fa; float la, ra;
    if (y > 0) {
        const float* rowa = rowc - Ww;
        fa = *(const float4*)(rowa + x4);
        la = (x4 > 0)      ? rowa[x4 - 1] : ninf;
        ra = (x4 + 4 < Ww) ? rowa[x4 + 4] : ninf;
    } else { fa = make_float4(ninf, ninf, ninf, ninf); la = ra = ninf; }
    float4 fb; float lb, rb;
    if (y + 1 < Hh) {
        const float* rowb = rowc + Ww;
        fb = *(const float4*)(rowb + x4);
        lb = (x4 > 0)      ? rowb[x4 - 1] : ninf;
        rb = (x4 + 4 < Ww) ? rowb[x4 + 4] : ninf;
    } else { fb = make_float4(ninf, ninf, ninf, ninf); lb = rb = ninf; }

    float cm0 = fmax3(la, lc, lb);
    float cm1 = fmax3(fa.x, f.x, fb.x);
    float cm2 = fmax3(fa.y, f.y, fb.y);
    float cm3 = fmax3(fa.z, f.z, fb.z);
    float cm4 = fmax3(fa.w, f.w, fb.w);
    float cm5 = fmax3(ra, rc, rb);

    if (f.x >= T0F && f.x >= fmax3(cm0, cm1, cm2)) mb |= 1u;
    if (f.y >= T0F && f.y >= fmax3(cm1, cm2, cm3)) mb |= 2u;
    if (f.z >= T0F && f.z >= fmax3(cm2, cm3, cm4)) mb |= 4u;
    if (f.w >= T0F && f.w >= fmax3(cm3, cm4, cm5)) mb |= 8u;
    return mb;
}

// ---------------- kernel 1: direct-from-global 3x3 NMS, 4 quads/thread ----------------
__global__ void nms_collect(const float* __restrict__ hm) {
    __shared__ int wsum[NWARP];
    __shared__ int wbase[NWARP];
    __shared__ int s_gbase;

    int tid = threadIdx.x;
    unsigned lane = tid & 31u;
    int wid = tid >> 5;

    int slice = blockIdx.y;
    int q0    = blockIdx.x * CHUNK + tid;      // quads q0 + i*NMS_T, i in [0,4)
    const float* base = hm + (size_t)slice * HWsz;

    unsigned mask16 = 0;
#pragma unroll
    for (int i = 0; i < QPT; i++) {
        int q  = q0 + i * NMS_T;
        int y  = q / QPR;
        int x4 = (q - y * QPR) * 4;
        const float* rowc = base + y * Ww;
        float4 f = *(const float4*)(rowc + x4);
        float qm = fmaxf(fmaxf(f.x, f.y), fmaxf(f.z, f.w));
        if (qm >= T0F) {
            mask16 |= nms_quad(rowc, f, y, x4) << (i * 4);
        }
    }

    int cnt = __popc(mask16);

    // block-wide exclusive scan (order canonicalized later by the full sort)
    int inc = cnt;
#pragma unroll
    for (int d = 1; d < 32; d <<= 1) {
        int o = __shfl_up_sync(0xffffffffu, inc, d);
        if ((int)lane >= d) inc += o;
    }
    if (lane == 31) wsum[wid] = inc;
    __syncthreads();
    if (wid == 0) {
        int s = (lane < NWARP) ? wsum[lane] : 0;
#pragma unroll
        for (int d = 1; d < NWARP; d <<= 1) {
            int o = __shfl_up_sync(0xffffffffu, s, d);
            if ((int)lane >= d) s += o;
        }
        if (lane < NWARP) wbase[lane] = s - wsum[lane];
        if (lane == NWARP - 1) s_gbase = s ? atomicAdd(&g_cnt[slice], s) : 0;
    }
    __syncthreads();

    if (mask16) {
        int off = s_gbase + wbase[wid] + (inc - cnt);
        ull* dst = g_cand + (size_t)slice * HWsz;
#pragma unroll
        for (int i = 0; i < QPT; i++) {
            unsigned mb = (mask16 >> (i * 4)) & 0xFu;
            if (!mb) continue;
            int q  = q0 + i * NMS_T;
            int y  = q / QPR;
            int x4 = (q - y * QPR) * 4;
            unsigned pbase = (unsigned)(y * Ww + x4);
            while (mb) {
                int j = __ffs(mb) - 1; mb &= mb - 1;
                float v = base[pbase + j];           // L1-hot reload
                dst[off++] = make_key(v, pbase + j);
            }
        }
    }
}

// ---------------- bitonic sort (descending) ----------------
template <int M>
__device__ void bitonic_desc(ull* buf, int tid, int nt) {
    for (int k = 2; k <= M; k <<= 1) {
        for (int j = k >> 1; j > 0; j >>= 1) {
            for (int i = tid; i < M; i += nt) {
                int ij = i ^ j;
                if (ij > i) {
                    bool dir = ((i & k) == 0);          // true -> descending segment
                    ull a = buf[i], b = buf[ij];
                    if ((a < b) == dir) { buf[i] = b; buf[ij] = a; }
                }
            }
            __syncthreads();
        }
    }
}

// ---------------- kernel 2: per-slice exact top-100, leveled 12-bit radix ----------------
__global__ void select_topk(const float* __restrict__ hm) {
    __shared__ int hist[4096];
    __shared__ ull buf[2048];
    __shared__ int wsc[NWARP];
    __shared__ int s_bin, s_pre, s_mexp, s_m;

    int bc  = blockIdx.x;
    int tid = threadIdx.x;
    const int nt = 512;
    unsigned lane = tid & 31u;
    int wid = tid >> 5;

    int n = g_cnt[bc];
    ull* cand = g_cand + (size_t)bc * HWsz;

    // ---- exact fallback: too few fast candidates -> rebuild ALL survivors inline.
    // (Never executes for this input: fast count ~3.1K >> 100.)
    if (n < KDET) {
        if (tid == 0) s_m = 0;
        __syncthreads();
        const float* base = hm + (size_t)bc * HWsz;
        for (int p = tid; p < HWsz; p += nt) {
            float v = base[p];
            int y = p / Ww, x = p - y * Ww;
            bool sv = true;
#pragma unroll
            for (int dy = -1; dy <= 1; dy++)
#pragma unroll
                for (int dx = -1; dx <= 1; dx++) {
                    if ((dy | dx) == 0) continue;
                    int yy = y + dy, xx = x + dx;
                    if ((unsigned)yy < (unsigned)Hh && (unsigned)xx < (unsigned)Ww)
                        sv = sv && (v >= base[yy * Ww + xx]);
                }
            if (sv) { int o = atomicAdd(&s_m, 1); cand[o] = make_key(v, (unsigned)p); }
        }
        __syncthreads();
        n = s_m;
        __syncthreads();
    }
    if (tid == 0) s_m = 0;

    // ---- leveled 12-bit radix: find pref with |{k >= pref}| in [K, 2048]
    ull pref = 0;
    int prevcum = 0;
    int shift = 52;
#pragma unroll 1
    for (int level = 0; level < 4; level++) {
        for (int i = tid; i < 4096; i += nt) hist[i] = 0;
        if (tid == 0) { s_bin = 0; s_pre = prevcum; s_mexp = prevcum; }
        __syncthreads();

        bool top = (level == 0);
        for (int i = tid; i < n; i += nt) {
            ull k = cand[i];
            if (top || ((k >> (shift + 12)) == (pref >> (shift + 12))))
                atomicAdd(&hist[(int)((k >> shift) & 4095)], 1);
        }
        __syncthreads();

        // parallel suffix scan: thread t owns descending chunk of 8 bins
        int lo = 4096 - 8 * (tid + 1);
        int cs = 0;
#pragma unroll
        for (int j = 0; j < 8; j++) cs += hist[lo + j];
        int inc = cs;
#pragma unroll
        for (int d = 1; d < 32; d <<= 1) {
            int o = __shfl_up_sync(0xffffffffu, inc, d);
            if ((int)lane >= d) inc += o;
        }
        if (lane == 31) wsc[wid] = inc;
        __syncthreads();
        int wpre = 0;
        {
            int s = (lane < NWARP) ? wsc[lane] : 0;
#pragma unroll
            for (int d = 1; d < NWARP; d <<= 1) {
                int o = __shfl_up_sync(0xffffffffu, s, d);
                if ((int)lane >= d) s += o;
            }
            s = __shfl_sync(0xffffffffu, s, (wid == 0) ? 0 : (wid - 1));
            wpre = (wid == 0) ? 0 : s;
        }
        int pre = prevcum + wpre + (inc - cs);
        if (pre < KDET && pre + cs >= KDET) {     // exactly one crossing thread
            int cum = pre;
            for (int j = 7; j >= 0; j--) {
                int bin = lo + j;
                int c = hist[bin];
                if (cum + c >= KDET) { s_bin = bin; s_pre = cum; s_mexp = cum + c; break; }
                cum += c;
            }
        }
        __syncthreads();
        pref |= ((ull)s_bin) << shift;
        prevcum = s_pre;
        int mexp = s_mexp;
        __syncthreads();
        if (mexp <= 2048 || shift == 16) break;
        shift -= 12;
    }

    // ---- single collect pass + sort
    for (int i = tid; i < n; i += nt) {
        ull k = cand[i];
        if (k >= pref) {
            int p = atomicAdd(&s_m, 1);
            if (p < 2048) buf[p] = k;
        }
    }
    __syncthreads();
    int m = min(s_m, 2048);

    if (m <= 512) {
        for (int i = tid + m; i < 512; i += nt) buf[i] = 0xFFFFFFFFull;  // value 0, pix 0
        __syncthreads();
        bitonic_desc<512>(buf, tid, nt);
    } else {
        for (int i = tid + m; i < 2048; i += nt) buf[i] = 0xFFFFFFFFull;
        __syncthreads();
        bitonic_desc<2048>(buf, tid, nt);
    }

    if (tid < KDET) g_top1[bc * KDET + tid] = buf[tid];

    // epilogue: reset counter for the next graph replay
    if (tid == 0) g_cnt[bc] = 0;
}

// ---------------- kernel 3: per-batch 3-way merge-rank + geometry epilogue ----------------
// Three per-class top-100 lists are sorted descending. Global rank of candidate i =
// own index + (# strictly-greater keys in the other lists via binary search). Re-keyed
// 64-bit keys are pairwise distinct => ranks form a permutation == jax top_k order.
__global__ void finalize(const float* __restrict__ reg,
                         const float* __restrict__ trans,
                         const float* __restrict__ Kmat,
                         const float* __restrict__ size2,
                         const float* __restrict__ hcam,
                         const float* __restrict__ dimsIn,
                         float* __restrict__ out) {
    __shared__ ull s_key[3 * KDET];

    int b = blockIdx.x, tid = threadIdx.x;

    unsigned pix = 0;
    if (tid < 3 * KDET) {
        ull k1 = g_top1[b * (3 * KDET) + tid];   // tid = c*100 + j
        pix = 0xFFFFFFFFu - (unsigned)(k1 & 0xFFFFFFFFu);
        if (pix >= (unsigned)HWsz) pix = 0;
        // re-key with flattened C*K position for the second-stage tie-break
        s_key[tid] = (k1 & 0xFFFFFFFF00000000ull) |
                     (ull)(0xFFFFFFFFu - (unsigned)tid);
    }
    __syncthreads();

    if (tid < 3 * KDET) {
        // own regression gathers (issued early; high MLP overlaps the ranking)
        const float* rb = reg + (size_t)b * 4 * HWsz;
        float dv_delta = rb[0 * HWsz + pix];
        float off_u    = rb[1 * HWsz + pix];
        float ori0     = rb[2 * HWsz + pix];
        float ori1     = rb[3 * HWsz + pix];

        ull x = s_key[tid];
        int a = tid / KDET;
        int r = tid - a * KDET;                  // own-list index
#pragma unroll
        for (int L = 0; L < 3; L++) {
            if (L == a) continue;
            const ull* Ls = s_key + L * KDET;
            int lo = 0, hi = KDET;
            while (lo < hi) {                    // count of keys > x (descending list)
                int mid = (lo + hi) >> 1;
                if (Ls[mid] > x) lo = mid + 1; else hi = mid;
            }
            r += lo;
        }

        if (r < KDET) {
            float score = __uint_as_float((unsigned)(x >> 32));
            int clsI = a;

            int ysI = pix / Ww;
            int xsI = pix - ysI * Ww;
            float xs = (float)xsI, ys = (float)ysI;

            // 3x3 inverse of trans_mat (first row needed for img_x)
            const float* T = trans + b * 9;
            float a00=T[0],a01=T[1],a02=T[2],a10=T[3],a11=T[4],a12=T[5],a20=T[6],a21=T[7],a22=T[8];
            float det = a00*(a11*a22 - a12*a21) - a01*(a10*a22 - a12*a20) + a02*(a10*a21 - a11*a20);
            float id = 1.0f / det;
            float i00=(a11*a22-a12*a21)*id, i01=(a02*a21-a01*a22)*id, i02=(a01*a12-a02*a11)*id;

            float ptx = xs + off_u, pty = ys;
            float img_x = i00*ptx + i01*pty + i02;

            const float* Km = Kmat + b * 9;
            float fx = Km[0], cxk = Km[2], fy = Km[4];

            float h = hcam[b];
            float d0 = dimsIn[b*3+0], d1 = dimsIn[b*3+1], d2 = dimsIn[b*3+2];
            if (!isfinite(d0)) d0 = 3.88f;
            if (!isfinite(d1)) d1 = 1.63f;
            if (!isfinite(d2)) d2 = 1.53f;

            float h_ref = h - d1 * 0.5f;
            float fyh = fy * fabsf(h_ref);
            float log_dv_ref = logf(fmaxf(fyh, 1e-7f) / 28.01f);
            float log_dv = fminf(fmaxf(log_dv_ref + dv_delta, -4.0f), 8.0f);
            float depth = fminf(fmaxf(fyh * expf(-log_dv), 0.5f), 120.0f);
            float pxl = (img_x - cxk) * depth / fx;

            float ray = atanf(pxl / (depth + 1e-7f));
            float alpha = atanf(ori0 / (ori1 + 1e-7f)) + (ori1 >= 0.0f ? -HALF_PI_F : HALF_PI_F);
            float roty = alpha + ray;
            if (roty >  PI_F) roty -= 2.0f * PI_F;
            if (roty < -PI_F) roty += 2.0f * PI_F;
            float cs = cosf(roty), sn = sinf(roty);

            const float cx8[8] = {-0.5f, 0.5f, 0.5f, 0.5f, 0.5f,-0.5f,-0.5f,-0.5f};
            const float cy8[8] = {-1.0f,-1.0f, 0.0f, 0.0f,-1.0f,-1.0f, 0.0f, 0.0f};
            const float cz8[8] = {-0.5f,-0.5f,-0.5f, 0.5f, 0.5f, 0.5f, 0.5f,-0.5f};

            float umin =  3.4e38f, umax = -3.4e38f, vmin = 3.4e38f, vmax = -3.4e38f;
#pragma unroll
            for (int i = 0; i < 8; i++) {
                float xc = d0 * cx8[i], yc = d1 * cy8[i], zc = d2 * cz8[i];
                float bx =  cs * xc + sn * zc + pxl;
                float by =  yc + h;
                float bz = -sn * xc + cs * zc + depth;
                float up = Km[0]*bx + Km[1]*by + Km[2]*bz;
                float vp = Km[3]*bx + Km[4]*by + Km[5]*bz;
                float wp = Km[6]*bx + Km[7]*by + Km[8]*bz;
                float u = up / wp, v = vp / wp;
                umin = fminf(umin, u); umax = fmaxf(umax, u);
                vmin = fminf(vmin, v); vmax = fmaxf(vmax, v);
            }
            float img_w = size2[0], img_h = size2[1];
            float xmin = fminf(fmaxf(umin, 0.0f), img_w);
            float xmax = fminf(fmaxf(umax, 0.0f), img_w);
            float ymin = fminf(fmaxf(vmin, 0.0f), img_h);
            float ymax = fminf(fmaxf(vmax, 0.0f), img_h);

            float keep = (score > 0.25f) ? 1.0f : 0.0f;

            float o[14];
            o[0]  = (float)clsI;
            o[1]  = alpha;
            o[2]  = xmin; o[3] = ymin; o[4] = xmax; o[5] = ymax;
            o[6]  = d1;   o[7] = d2;   o[8] = d0;          // roll(dims, -1)
            o[9]  = pxl;  o[10] = h;   o[11] = depth;
            o[12] = roty;
            o[13] = score;

            float* dst = out + (size_t)(b * KDET + r) * 14;
#pragma unroll
            for (int c = 0; c < 14; c++) dst[c] = o[c] * keep;
        }
    }
}

// ---------------- launch ----------------
extern "C" void kernel_launch(void* const* d_in, const int* in_sizes, int n_in,
                              void* d_out, int out_size) {
    const float* hm    = (const float*)d_in[0];
    const float* reg   = (const float*)d_in[1];
    const float* trans = (const float*)d_in[2];
    const float* Kmat  = (const float*)d_in[3];
    const float* size2 = (const float*)d_in[4];
    const float* hcam  = (const float*)d_in[5];
    const float* dims  = (const float*)d_in[6];
    float* out = (float*)d_out;

    dim3 grid(BLK_PER_SLICE, BC);              // (26, 96)
    nms_collect<<<grid, NMS_T>>>(hm);
    select_topk<<<BC, 512>>>(hm);
    finalize<<<Bb, 320>>>(reg, trans, Kmat, size2, hcam, dims, out);
}